// round 5
// baseline (speedup 1.0000x reference)
#include <cuda_runtime.h>

// Problem constants
#define BB  16
#define NN  16384
#define SS  1024
#define CC  128
#define SEM 20

#define T   512            // threads per FPS block
#define PPT (NN / T)       // 32 points per thread

#define A0 (BB * SS * 3)   // sampled_xyz elems    = 49152
#define A1 (BB * CC * SS)  // feature gather elems = 2097152
#define A2 (BB * SS)       // labels               = 16384

// Scratch for selected indices (no allocation allowed)
__device__ int g_idx[BB * SS];

// Shared layout offsets (bytes)
#define OFF_XY   0
#define OFF_Z    (NN * 8)          // 131072
#define OFF_CNT  (NN * 12)         // 196608
#define OFF_RV   (OFF_CNT + 128)   // 32 floats for counts (20 used)
#define OFF_RI   (OFF_RV + 128)
#define OFF_BIDX (OFF_RI + 128)
#define SMEM_BYTES (OFF_BIDX + 16)

__global__ __launch_bounds__(T, 1)
void fps_kernel(const float* __restrict__ xyz, const int* __restrict__ label)
{
    extern __shared__ char smem[];
    float2* s_xy  = (float2*)(smem + OFF_XY);
    float*  s_z   = (float*) (smem + OFF_Z);
    float*  s_cnt = (float*) (smem + OFF_CNT);
    float*  s_rv  = (float*) (smem + OFF_RV);
    int*    s_ri  = (int*)   (smem + OFF_RI);
    int*    s_bidx= (int*)   (smem + OFF_BIDX);

    const int b   = blockIdx.x;
    const int tid = threadIdx.x;
    const float* bx = xyz + (size_t)b * NN * 3;
    const int*   bl = label + (size_t)b * NN;

    if (tid < SEM) s_cnt[tid] = 0.0f;
    __syncthreads();

    // Stage xyz into shared (float2 xy + float z) and build class histogram.
    #pragma unroll 8
    for (int i = tid; i < NN; i += T) {
        float x = bx[3 * i + 0];
        float y = bx[3 * i + 1];
        float z = bx[3 * i + 2];
        s_xy[i] = make_float2(x, y);
        s_z[i]  = z;
        atomicAdd(&s_cnt[bl[i]], 1.0f);   // exact integer sums < 2^24
    }
    __syncthreads();

    // Per-thread state: M[k] = rn(min_d * w). Bitwise equal to the reference's
    // score rn(min_d)*w because rounding is monotone and w > 0:
    //   min(rn(a*w), rn(b*w)) == rn(min(a,b)*w).
    float M[PPT], w[PPT];
    #pragma unroll
    for (int k = 0; k < PPT; k++) {
        int p = tid + k * T;
        w[k] = s_cnt[bl[p]];
        M[k] = 1e10f * w[k];              // matches min(1e10, d)*w after iter 1
    }

    int cur = 0;
    if (tid == 0) g_idx[b * SS + 0] = 0;
    __syncthreads();

    for (int s = 1; s < SS; s++) {
        const float lx = s_xy[cur].x;
        const float ly = s_xy[cur].y;
        const float lz = s_z[cur];

        // Phase 1: update M, track only the max value (FMNMX, cheap).
        float best = -1.0f;
        #pragma unroll
        for (int k = 0; k < PPT; k++) {
            int p = tid + k * T;
            float2 xy = s_xy[p];
            float  z  = s_z[p];
            // XLA-contracted distance: ((dx*dx + dy*dy) + dz*dz) with FMA
            // contraction as LLVM emits it: fma(dz,dz, fma(dy,dy, dx*dx)).
            float dx = __fadd_rn(xy.x, -lx);
            float dy = __fadd_rn(xy.y, -ly);
            float dz = __fadd_rn(z,    -lz);
            float d  = __fmaf_rn(dz, dz,
                        __fmaf_rn(dy, dy,
                         __fmul_rn(dx, dx)));
            float m  = fminf(M[k], __fmul_rn(d, w[k]));
            M[k] = m;
            best = fmaxf(best, m);
        }

        // Phase 2: recover the lowest local index attaining best.
        // Descending scan with overwrite -> lowest k (== lowest global p,
        // since p = tid + k*T is increasing in k). Matches jnp.argmax.
        int bi = 0;
        #pragma unroll
        for (int k = PPT - 1; k >= 0; k--) {
            if (M[k] == best) bi = tid + k * T;
        }

        // Warp argmax reduce (lexicographic: max value, then min index)
        #pragma unroll
        for (int off = 16; off > 0; off >>= 1) {
            float ov = __shfl_xor_sync(0xffffffffu, best, off);
            int   oi = __shfl_xor_sync(0xffffffffu, bi,   off);
            if (ov > best || (ov == best && oi < bi)) { best = ov; bi = oi; }
        }
        const int wid = tid >> 5, lane = tid & 31;
        if (lane == 0) { s_rv[wid] = best; s_ri[wid] = bi; }
        __syncthreads();

        if (wid == 0) {
            best = (lane < (T / 32)) ? s_rv[lane] : -1.0f;
            bi   = (lane < (T / 32)) ? s_ri[lane] : 0x7fffffff;
            #pragma unroll
            for (int off = 16; off > 0; off >>= 1) {
                float ov = __shfl_xor_sync(0xffffffffu, best, off);
                int   oi = __shfl_xor_sync(0xffffffffu, bi,   off);
                if (ov > best || (ov == best && oi < bi)) { best = ov; bi = oi; }
            }
            if (lane == 0) { *s_bidx = bi; g_idx[b * SS + s] = bi; }
        }
        __syncthreads();
        cur = *s_bidx;
    }
}

__global__ void gather_kernel(const float* __restrict__ xyz,
                              const float* __restrict__ feat,
                              const int*   __restrict__ label,
                              float* __restrict__ out)
{
    int i = blockIdx.x * blockDim.x + threadIdx.x;
    const int total = A0 + A1 + A2;
    if (i >= total) return;

    if (i < A0) {
        // sampled_xyz [B, S, 3]
        int b = i / (SS * 3);
        int r = i - b * SS * 3;
        int s = r / 3;
        int d = r - s * 3;
        int id = g_idx[b * SS + s];
        out[i] = xyz[((size_t)b * NN + id) * 3 + d];
    } else if (i < A0 + A1) {
        // sample_seg_feature [B, C, S]
        int j = i - A0;
        int b = j / (CC * SS);
        int r = j - b * CC * SS;
        int c = r / SS;
        int s = r - c * SS;
        int id = g_idx[b * SS + s];
        out[i] = feat[((size_t)b * CC + c) * NN + id];
    } else {
        // sample_seg_label [B, S] cast to float
        int j = i - A0 - A1;
        int b = j / SS;
        int s = j - b * SS;
        int id = g_idx[b * SS + s];
        out[i] = (float)label[(size_t)b * NN + id];
    }
}

extern "C" void kernel_launch(void* const* d_in, const int* in_sizes, int n_in,
                              void* d_out, int out_size)
{
    const float* xyz   = (const float*)d_in[0];
    const float* feat  = (const float*)d_in[1];
    const int*   label = (const int*)  d_in[2];
    float*       out   = (float*)d_out;

    cudaFuncSetAttribute(fps_kernel,
                         cudaFuncAttributeMaxDynamicSharedMemorySize,
                         SMEM_BYTES);

    fps_kernel<<<BB, T, SMEM_BYTES>>>(xyz, label);

    const int total = A0 + A1 + A2;
    gather_kernel<<<(total + 255) / 256, 256>>>(xyz, feat, label, out);
}

// round 6
// speedup vs baseline: 1.1222x; 1.1222x over previous
#include <cuda_runtime.h>
#include <cstdint>

// Problem constants
#define BB  16
#define NN  16384
#define SS  1024
#define CC  128
#define SEM 20

// Cluster FPS config
#define CL   8              // CTAs per cluster (one cluster per batch)
#define TC   256            // threads per CTA
#define NLOC (NN / CL)      // 2048 points per CTA
#define PL   (NLOC / TC)    // 8 points per thread
#define NW   (TC / 32)      // 8 warps

#define A0 (BB * SS * 3)    // sampled_xyz elems    = 49152
#define A1 (BB * CC * SS)   // feature gather elems = 2097152
#define A2 (BB * SS)        // labels               = 16384

__device__ int g_idx[BB * SS];

// ---------------- PTX helpers ----------------
static __device__ __forceinline__ uint32_t smem_u32(const void* p) {
    uint32_t a;
    asm("{ .reg .u64 t; cvta.to.shared.u64 t, %1; cvt.u32.u64 %0, t; }"
        : "=r"(a) : "l"(p));
    return a;
}
static __device__ __forceinline__ uint32_t mapa_u32(uint32_t a, uint32_t rank) {
    uint32_t d;
    asm("mapa.shared::cluster.u32 %0, %1, %2;" : "=r"(d) : "r"(a), "r"(rank));
    return d;
}
static __device__ __forceinline__ void st_cluster_u32(uint32_t a, uint32_t v) {
    asm volatile("st.shared::cluster.b32 [%0], %1;" :: "r"(a), "r"(v) : "memory");
}
static __device__ __forceinline__ void arrive_cluster(uint32_t a) {
    asm volatile("mbarrier.arrive.release.cluster.shared::cluster.b64 _, [%0];"
                 :: "r"(a) : "memory");
}
static __device__ __forceinline__ void bar_init(uint32_t a, uint32_t cnt) {
    asm volatile("mbarrier.init.shared.b64 [%0], %1;" :: "r"(a), "r"(cnt) : "memory");
}
static __device__ __forceinline__ void wait_parity_cluster(uint32_t a, uint32_t ph) {
    asm volatile(
        "{\n\t.reg .pred P;\n\t"
        "WL_%=:\n\t"
        "mbarrier.try_wait.parity.acquire.cluster.shared::cta.b64 P, [%0], %1, 0x989680;\n\t"
        "@P bra.uni WD_%=;\n\t"
        "bra.uni WL_%=;\n\t"
        "WD_%=:\n\t}"
        :: "r"(a), "r"(ph) : "memory");
}

// ---------------- FPS: one 8-CTA cluster per batch ----------------
__global__ __launch_bounds__(TC, 1) __cluster_dims__(CL, 1, 1)
void fps_kernel(const float* __restrict__ xyz, const int* __restrict__ label)
{
    __shared__ float2 s_xy[NLOC];
    __shared__ float  s_z[NLOC];
    __shared__ float  s_cnt[32];
    __shared__ float  s_rv[NW];
    __shared__ int    s_ri[NW];
    // Candidate records, double-buffered by iteration parity:
    // [buf][srcCTA][8 words: val, gidx, x, y, z, pad...]
    __shared__ __align__(16) float s_cand[2 * CL * 8];
    __shared__ __align__(8) unsigned long long s_bar;

    const int b    = blockIdx.x / CL;
    const int rank = blockIdx.x % CL;
    const int tid  = threadIdx.x;
    const int base = rank * NLOC;
    const float* bx = xyz + (size_t)b * NN * 3;
    const int*   bl = label + (size_t)b * NN;

    const uint32_t bar_a  = smem_u32(&s_bar);
    const uint32_t cand_a = smem_u32(s_cand);

    if (tid == 0) bar_init(bar_a, CL);
    if (tid < 32) s_cnt[tid] = 0.0f;
    __syncthreads();

    // Class histogram over the FULL batch (weights need global counts).
    for (int i = tid; i < NN; i += TC) atomicAdd(&s_cnt[bl[i]], 1.0f);
    // Stage this CTA's shard of xyz.
    for (int i = tid; i < NLOC; i += TC) {
        int g = base + i;
        s_xy[i] = make_float2(bx[3 * g + 0], bx[3 * g + 1]);
        s_z[i]  = bx[3 * g + 2];
    }
    __syncthreads();

    // Per-thread state. M[k] = rn(min_d * w), bitwise-equivalent score to the
    // reference's rn(min_d)*w by monotonicity of rounding (w >= 1).
    float M[PL], w[PL];
    #pragma unroll
    for (int k = 0; k < PL; k++) {
        int p = tid + k * TC;
        w[k] = s_cnt[bl[base + p]];
        M[k] = 1e10f * w[k];
    }

    // First selected point is global index 0 (in rank 0's shard; read via gmem).
    float cx = bx[0], cy = bx[1], cz = bx[2];
    if (rank == 0 && tid == 0) g_idx[b * SS] = 0;

    const int wid = tid >> 5, lane = tid & 31;

    // Precompute remote addresses (lane -> destination CTA == lane).
    uint32_t dst_bar = 0, dst_c0 = 0, dst_c1 = 0;
    if (wid == 0 && lane < CL) {
        dst_bar = mapa_u32(bar_a, (uint32_t)lane);
        dst_c0  = mapa_u32(cand_a + (uint32_t)(rank * 32),            (uint32_t)lane);
        dst_c1  = mapa_u32(cand_a + (uint32_t)((CL + rank) * 32),     (uint32_t)lane);
    }

    // All mbarriers must be initialized cluster-wide before any remote arrive.
    asm volatile("barrier.cluster.arrive.aligned;" ::: "memory");
    asm volatile("barrier.cluster.wait.aligned;" ::: "memory");

    for (int s = 1; s < SS; s++) {
        // ---- Phase 1: update M against (cx,cy,cz); track max score ----
        float best = -1.0f;
        #pragma unroll
        for (int k = 0; k < PL; k++) {
            int p = tid + k * TC;
            float2 xy = s_xy[p];
            float  z  = s_z[p];
            // XLA-contracted distance: fma(dz,dz, fma(dy,dy, dx*dx))
            float dx = __fadd_rn(xy.x, -cx);
            float dy = __fadd_rn(xy.y, -cy);
            float dz = __fadd_rn(z,    -cz);
            float d  = __fmaf_rn(dz, dz, __fmaf_rn(dy, dy, __fmul_rn(dx, dx)));
            float m  = fminf(M[k], __fmul_rn(d, w[k]));
            M[k] = m;
            best = fmaxf(best, m);
        }
        // ---- Phase 2: lowest local index attaining best ----
        int bi = 0;
        #pragma unroll
        for (int k = PL - 1; k >= 0; k--)
            if (M[k] == best) bi = tid + k * TC;

        // ---- Warp reduce (max value, min index) ----
        #pragma unroll
        for (int off = 16; off > 0; off >>= 1) {
            float ov = __shfl_xor_sync(0xffffffffu, best, off);
            int   oi = __shfl_xor_sync(0xffffffffu, bi,   off);
            if (ov > best || (ov == best && oi < bi)) { best = ov; bi = oi; }
        }
        if (lane == 0) { s_rv[wid] = best; s_ri[wid] = bi; }
        __syncthreads();

        // ---- CTA reduce + all-to-all candidate exchange (warp 0) ----
        if (wid == 0) {
            float v  = (lane < NW) ? s_rv[lane] : -1.0f;
            int   li = (lane < NW) ? s_ri[lane] : 0x7fffffff;
            #pragma unroll
            for (int off = 4; off > 0; off >>= 1) {
                float ov = __shfl_xor_sync(0xffffffffu, v,  off);
                int   oi = __shfl_xor_sync(0xffffffffu, li, off);
                if (ov > v || (ov == v && oi < li)) { v = ov; li = oi; }
            }
            if (lane < CL) {
                // lanes 0..7 all hold the CTA winner; lane r sends to CTA r.
                float wx = s_xy[li].x, wy = s_xy[li].y, wz = s_z[li];
                int gi = base + li;
                uint32_t dst = (s & 1) ? dst_c1 : dst_c0;
                st_cluster_u32(dst + 0,  __float_as_uint(v));
                st_cluster_u32(dst + 4,  (uint32_t)gi);
                st_cluster_u32(dst + 8,  __float_as_uint(wx));
                st_cluster_u32(dst + 12, __float_as_uint(wy));
                st_cluster_u32(dst + 16, __float_as_uint(wz));
                arrive_cluster(dst_bar);   // release: stores above visible
            }
        }

        // ---- Wait for all 8 candidates; every warp reduces them ----
        wait_parity_cluster(bar_a, (uint32_t)((s - 1) & 1));

        const float* cb = &s_cand[(s & 1) * CL * 8];
        float v; int gi; float wx, wy, wz;
        if (lane < CL) {
            v  = cb[lane * 8 + 0];
            gi = ((const int*)cb)[lane * 8 + 1];
            wx = cb[lane * 8 + 2];
            wy = cb[lane * 8 + 3];
            wz = cb[lane * 8 + 4];
        } else { v = -1.0f; gi = 0x7fffffff; wx = wy = wz = 0.0f; }
        #pragma unroll
        for (int off = 4; off > 0; off >>= 1) {
            float ov = __shfl_xor_sync(0xffffffffu, v,  off);
            int   oi = __shfl_xor_sync(0xffffffffu, gi, off);
            float ox = __shfl_xor_sync(0xffffffffu, wx, off);
            float oy = __shfl_xor_sync(0xffffffffu, wy, off);
            float oz = __shfl_xor_sync(0xffffffffu, wz, off);
            if (ov > v || (ov == v && oi < gi)) { v = ov; gi = oi; wx = ox; wy = oy; wz = oz; }
        }
        gi = __shfl_sync(0xffffffffu, gi, 0);
        cx = __shfl_sync(0xffffffffu, wx, 0);
        cy = __shfl_sync(0xffffffffu, wy, 0);
        cz = __shfl_sync(0xffffffffu, wz, 0);
        if (rank == 0 && tid == 0) g_idx[b * SS + s] = gi;
    }

    // Keep cluster alive until all remote traffic has retired.
    asm volatile("barrier.cluster.arrive.aligned;" ::: "memory");
    asm volatile("barrier.cluster.wait.aligned;" ::: "memory");
}

// ---------------- Gather ----------------
__global__ void gather_kernel(const float* __restrict__ xyz,
                              const float* __restrict__ feat,
                              const int*   __restrict__ label,
                              float* __restrict__ out)
{
    int i = blockIdx.x * blockDim.x + threadIdx.x;
    const int total = A0 + A1 + A2;
    if (i >= total) return;

    if (i < A0) {
        int b = i / (SS * 3);
        int r = i - b * SS * 3;
        int s = r / 3;
        int d = r - s * 3;
        int id = g_idx[b * SS + s];
        out[i] = xyz[((size_t)b * NN + id) * 3 + d];
    } else if (i < A0 + A1) {
        int j = i - A0;
        int b = j / (CC * SS);
        int r = j - b * CC * SS;
        int c = r / SS;
        int s = r - c * SS;
        int id = g_idx[b * SS + s];
        out[i] = feat[((size_t)b * CC + c) * NN + id];
    } else {
        int j = i - A0 - A1;
        int b = j / SS;
        int s = j - b * SS;
        int id = g_idx[b * SS + s];
        out[i] = (float)label[(size_t)b * NN + id];
    }
}

extern "C" void kernel_launch(void* const* d_in, const int* in_sizes, int n_in,
                              void* d_out, int out_size)
{
    const float* xyz   = (const float*)d_in[0];
    const float* feat  = (const float*)d_in[1];
    const int*   label = (const int*)  d_in[2];
    float*       out   = (float*)d_out;

    fps_kernel<<<BB * CL, TC>>>(xyz, label);

    const int total = A0 + A1 + A2;
    gather_kernel<<<(total + 255) / 256, 256>>>(xyz, feat, label, out);
}

// round 8
// speedup vs baseline: 1.1671x; 1.0400x over previous
#include <cuda_runtime.h>
#include <cstdint>

// Problem constants
#define BB  16
#define NN  16384
#define SS  1024
#define CC  128
#define SEM 20

// Cluster FPS config
#define CL   8              // CTAs per cluster (one cluster per batch)
#define TC   256            // threads per CTA
#define NLOC (NN / CL)      // 2048 points per CTA
#define PL   (NLOC / TC)    // 8 points per thread
#define NW   (TC / 32)      // 8 warps

#define A0 (BB * SS * 3)    // sampled_xyz elems    = 49152
#define A1 (BB * CC * SS)   // feature gather elems = 2097152
#define A2 (BB * SS)        // labels               = 16384

__device__ int g_idx[BB * SS];

// ---------------- PTX helpers ----------------
static __device__ __forceinline__ uint32_t smem_u32(const void* p) {
    uint32_t a;
    asm("{ .reg .u64 t; cvta.to.shared.u64 t, %1; cvt.u32.u64 %0, t; }"
        : "=r"(a) : "l"(p));
    return a;
}
static __device__ __forceinline__ uint32_t mapa_u32(uint32_t a, uint32_t rank) {
    uint32_t d;
    asm("mapa.shared::cluster.u32 %0, %1, %2;" : "=r"(d) : "r"(a), "r"(rank));
    return d;
}
static __device__ __forceinline__ void st_cluster_u64(uint32_t a, uint64_t v) {
    asm volatile("st.shared::cluster.b64 [%0], %1;" :: "r"(a), "l"(v) : "memory");
}
static __device__ __forceinline__ void st_cluster_u32(uint32_t a, uint32_t v) {
    asm volatile("st.shared::cluster.b32 [%0], %1;" :: "r"(a), "r"(v) : "memory");
}
static __device__ __forceinline__ void arrive_cluster(uint32_t a) {
    asm volatile("mbarrier.arrive.release.cluster.shared::cluster.b64 _, [%0];"
                 :: "r"(a) : "memory");
}
static __device__ __forceinline__ void bar_init(uint32_t a, uint32_t cnt) {
    asm volatile("mbarrier.init.shared.b64 [%0], %1;" :: "r"(a), "r"(cnt) : "memory");
}
// Tight poll (no suspend hint): fast wakeup, only warp 0 polls.
static __device__ __forceinline__ void wait_parity_poll(uint32_t a, uint32_t ph) {
    uint32_t done;
    do {
        asm volatile(
            "{\n\t.reg .pred P;\n\t"
            "mbarrier.test_wait.parity.acquire.cluster.shared::cta.b64 P, [%1], %2;\n\t"
            "selp.b32 %0, 1, 0, P;\n\t}"
            : "=r"(done) : "r"(a), "r"(ph) : "memory");
    } while (!done);
}
// Warp max over NON-NEGATIVE float scores via u32 redux (IEEE order == uint
// order for non-negative floats). redux.sync.*.u32 is baseline sm_80+ PTX.
static __device__ __forceinline__ uint32_t redux_max_u32(uint32_t v) {
    uint32_t o;
    asm volatile("redux.sync.max.u32 %0, %1, 0xffffffff;" : "=r"(o) : "r"(v));
    return o;
}

// ---------------- FPS: one 8-CTA cluster per batch ----------------
__global__ __launch_bounds__(TC, 1) __cluster_dims__(CL, 1, 1)
void fps_kernel(const float* __restrict__ xyz, const int* __restrict__ label)
{
    __shared__ float2 s_xy[NLOC];
    __shared__ float  s_z[NLOC];
    __shared__ float  s_cnt[32];
    __shared__ unsigned long long s_pack;   // CTA-level {score_bits | ~idx}
    // Candidate records, double-buffered by iteration parity:
    // [buf][srcCTA][8 words: val, gidx, x, y, z, pad...]
    __shared__ __align__(16) float s_cand[2 * CL * 8];
    __shared__ float4 s_win;                // winner {x, y, z, gi-bits}
    __shared__ __align__(8) unsigned long long s_bar;

    const int b    = blockIdx.x / CL;
    const int rank = blockIdx.x % CL;
    const int tid  = threadIdx.x;
    const int base = rank * NLOC;
    const float* bx = xyz + (size_t)b * NN * 3;
    const int*   bl = label + (size_t)b * NN;

    const uint32_t bar_a  = smem_u32(&s_bar);
    const uint32_t cand_a = smem_u32(s_cand);

    if (tid == 0) { bar_init(bar_a, CL); s_pack = 0ULL; }
    if (tid < 32) s_cnt[tid] = 0.0f;
    __syncthreads();

    // Class histogram over the FULL batch (weights need global counts).
    for (int i = tid; i < NN; i += TC) atomicAdd(&s_cnt[bl[i]], 1.0f);
    // Stage this CTA's shard of xyz.
    for (int i = tid; i < NLOC; i += TC) {
        int g = base + i;
        s_xy[i] = make_float2(bx[3 * g + 0], bx[3 * g + 1]);
        s_z[i]  = bx[3 * g + 2];
    }
    __syncthreads();

    // Per-thread state. M[k] = rn(min_d * w), bitwise-equivalent score to the
    // reference's rn(min_d)*w by monotonicity of rounding (w >= 1).
    float M[PL], w[PL];
    #pragma unroll
    for (int k = 0; k < PL; k++) {
        int p = tid + k * TC;
        w[k] = s_cnt[bl[base + p]];
        M[k] = 1e10f * w[k];
    }

    float cx = bx[0], cy = bx[1], cz = bx[2];
    if (rank == 0 && tid == 0) g_idx[b * SS] = 0;

    const int wid = tid >> 5, lane = tid & 31;

    // Precompute remote addresses (destination CTA == lane).
    uint32_t dst_bar = 0, dst_c0 = 0, dst_c1 = 0;
    if (wid == 0 && lane < CL) {
        dst_bar = mapa_u32(bar_a, (uint32_t)lane);
        dst_c0  = mapa_u32(cand_a + (uint32_t)(rank * 32),        (uint32_t)lane);
        dst_c1  = mapa_u32(cand_a + (uint32_t)((CL + rank) * 32), (uint32_t)lane);
    }

    // All mbarriers must be initialized cluster-wide before any remote arrive.
    asm volatile("barrier.cluster.arrive.aligned;" ::: "memory");
    asm volatile("barrier.cluster.wait.aligned;" ::: "memory");

    for (int s = 1; s < SS; s++) {
        // ---- Phase 1: update M against (cx,cy,cz); track max score ----
        float best = 0.0f;   // scores are >= 0
        #pragma unroll
        for (int k = 0; k < PL; k++) {
            int p = tid + k * TC;
            float2 xy = s_xy[p];
            float  z  = s_z[p];
            // XLA-contracted distance: fma(dz,dz, fma(dy,dy, dx*dx))
            float dx = __fadd_rn(xy.x, -cx);
            float dy = __fadd_rn(xy.y, -cy);
            float dz = __fadd_rn(z,    -cz);
            float d  = __fmaf_rn(dz, dz, __fmaf_rn(dy, dy, __fmul_rn(dx, dx)));
            float m  = fminf(M[k], __fmul_rn(d, w[k]));
            M[k] = m;
            best = fmaxf(best, m);
        }
        // ---- Phase 2: lowest local index attaining this thread's best ----
        int bi = 0x7fffffff;
        #pragma unroll
        for (int k = PL - 1; k >= 0; k--)
            if (M[k] == best) bi = tid + k * TC;

        // ---- Warp reduce: u32 max on score bits, min index among maximal ----
        uint32_t bwb = redux_max_u32(__float_as_uint(best));
        unsigned bio = __reduce_min_sync(0xffffffffu,
                        (__float_as_uint(best) == bwb) ? (unsigned)bi : 0x7fffffffu);
        if (lane == 0)
            atomicMax(&s_pack,
                (((unsigned long long)bwb) << 32) |
                (unsigned long long)(~bio));
        __syncthreads();

        // ---- Warp 0: exchange + cluster reduce; others wait at next bar ----
        if (wid == 0) {
            unsigned long long pk = s_pack;
            if (lane == 0) s_pack = 0ULL;        // reset for next iter
            uint32_t vb = (uint32_t)(pk >> 32);
            int      li = (int)(~(uint32_t)pk);
            float2 xy = s_xy[li];
            float  z  = s_z[li];
            int    gi = base + li;

            if (lane < CL) {
                uint32_t dst = (s & 1) ? dst_c1 : dst_c0;
                st_cluster_u64(dst + 0,
                    ((uint64_t)(uint32_t)gi << 32) | (uint64_t)vb);
                st_cluster_u64(dst + 8,
                    ((uint64_t)__float_as_uint(xy.y) << 32) |
                     (uint64_t)__float_as_uint(xy.x));
                st_cluster_u32(dst + 16, __float_as_uint(z));
                arrive_cluster(dst_bar);         // release: stores visible
            }

            wait_parity_poll(bar_a, (uint32_t)((s - 1) & 1));

            const float* cb = &s_cand[(s & 1) * CL * 8];
            uint32_t rvb; unsigned rgi; float rx, ry, rz;
            if (lane < CL) {
                rvb = ((const unsigned*)cb)[lane * 8 + 0];
                rgi = ((const unsigned*)cb)[lane * 8 + 1];
                rx  = cb[lane * 8 + 2];
                ry  = cb[lane * 8 + 3];
                rz  = cb[lane * 8 + 4];
            } else { rvb = 0u; rgi = 0x7fffffffu; rx = ry = rz = 0.0f; }

            uint32_t vmaxb = redux_max_u32(rvb);
            unsigned gw = __reduce_min_sync(0xffffffffu,
                            (rvb == vmaxb) ? rgi : 0x7fffffffu);
            unsigned mk = __ballot_sync(0xffffffffu, (lane < CL) && (rgi == gw));
            int src = __ffs(mk) - 1;
            rx = __shfl_sync(0xffffffffu, rx, src);
            ry = __shfl_sync(0xffffffffu, ry, src);
            rz = __shfl_sync(0xffffffffu, rz, src);
            if (lane == 0) {
                s_win = make_float4(rx, ry, rz, __uint_as_float(gw));
                if (rank == 0) g_idx[b * SS + s] = (int)gw;
            }
        }
        __syncthreads();
        float4 wr = s_win;
        cx = wr.x; cy = wr.y; cz = wr.z;
    }

    // Keep cluster alive until all remote traffic has retired.
    asm volatile("barrier.cluster.arrive.aligned;" ::: "memory");
    asm volatile("barrier.cluster.wait.aligned;" ::: "memory");
}

// ---------------- Gather ----------------
__global__ void gather_kernel(const float* __restrict__ xyz,
                              const float* __restrict__ feat,
                              const int*   __restrict__ label,
                              float* __restrict__ out)
{
    int i = blockIdx.x * blockDim.x + threadIdx.x;
    const int total = A0 + A1 + A2;
    if (i >= total) return;

    if (i < A0) {
        int b = i / (SS * 3);
        int r = i - b * SS * 3;
        int s = r / 3;
        int d = r - s * 3;
        int id = g_idx[b * SS + s];
        out[i] = xyz[((size_t)b * NN + id) * 3 + d];
    } else if (i < A0 + A1) {
        int j = i - A0;
        int b = j / (CC * SS);
        int r = j - b * CC * SS;
        int c = r / SS;
        int s = r - c * SS;
        int id = g_idx[b * SS + s];
        out[i] = feat[((size_t)b * CC + c) * NN + id];
    } else {
        int j = i - A0 - A1;
        int b = j / SS;
        int s = j - b * SS;
        int id = g_idx[b * SS + s];
        out[i] = (float)label[(size_t)b * NN + id];
    }
}

extern "C" void kernel_launch(void* const* d_in, const int* in_sizes, int n_in,
                              void* d_out, int out_size)
{
    const float* xyz   = (const float*)d_in[0];
    const float* feat  = (const float*)d_in[1];
    const int*   label = (const int*)  d_in[2];
    float*       out   = (float*)d_out;

    fps_kernel<<<BB * CL, TC>>>(xyz, label);

    const int total = A0 + A1 + A2;
    gather_kernel<<<(total + 255) / 256, 256>>>(xyz, feat, label, out);
}

// round 9
// speedup vs baseline: 1.3173x; 1.1287x over previous
#include <cuda_runtime.h>
#include <cstdint>

// Problem constants
#define BB  16
#define NN  16384
#define SS  1024
#define CC  128
#define SEM 20

// Cluster FPS config
#define CL   2               // CTAs per cluster (one cluster per batch)
#define T    512             // threads per CTA
#define NLOC (NN / CL)       // 8192 points per CTA
#define PPT  (NLOC / T)      // 16 points per thread
#define NPAIR (PPT / 2)      // 8 packed pairs per thread
#define NW   (T / 32)        // 16 warps

#define A0 (BB * SS * 3)
#define A1 (BB * CC * SS)
#define A2 (BB * SS)

__device__ int g_idx[BB * SS];

// Dynamic smem layout (bytes)
#define OFF_XYZ  0                      // NLOC*12 = 98304 (x,y,z scalar arrays)
#define OFF_X    0
#define OFF_Y    (NLOC * 4)
#define OFF_Z    (NLOC * 8)
#define OFF_CNT  (NLOC * 12)            // 32 floats
#define OFF_WARP (OFF_CNT + 128)        // 16 x u64 {score, idx}
#define OFF_CAND (OFF_WARP + 128)       // 2 bufs x 24B peer records
#define OFF_WIN  (OFF_CAND + 64)        // float4 winner
#define SMEM_BYTES (OFF_WIN + 16)

// ---------------- PTX helpers ----------------
static __device__ __forceinline__ uint32_t smem_u32(const void* p) {
    uint32_t a;
    asm("{ .reg .u64 t; cvta.to.shared.u64 t, %1; cvt.u32.u64 %0, t; }"
        : "=r"(a) : "l"(p));
    return a;
}
static __device__ __forceinline__ uint32_t mapa_u32(uint32_t a, uint32_t rank) {
    uint32_t d;
    asm("mapa.shared::cluster.u32 %0, %1, %2;" : "=r"(d) : "r"(a), "r"(rank));
    return d;
}
static __device__ __forceinline__ void st_cl_u64(uint32_t a, uint64_t v) {
    asm volatile("st.shared::cluster.b64 [%0], %1;" :: "r"(a), "l"(v) : "memory");
}
static __device__ __forceinline__ void st_cl_rel_u64(uint32_t a, uint64_t v) {
    asm volatile("st.release.cluster.shared::cluster.b64 [%0], %1;"
                 :: "r"(a), "l"(v) : "memory");
}
static __device__ __forceinline__ uint32_t ld_acq_u32(uint32_t a) {
    uint32_t v;
    asm volatile("ld.acquire.cluster.shared::cta.b32 %0, [%1];"
                 : "=r"(v) : "r"(a) : "memory");
    return v;
}
static __device__ __forceinline__ uint32_t redux_max_u32(uint32_t v) {
    uint32_t o;
    asm volatile("redux.sync.max.u32 %0, %1, 0xffffffff;" : "=r"(o) : "r"(v));
    return o;
}
// Packed f32x2 (per-lane bitwise identical to scalar rn ops)
static __device__ __forceinline__ uint64_t pk2(float lo, float hi) {
    uint64_t r;
    asm("mov.b64 %0, {%1, %2};"
        : "=l"(r) : "r"(__float_as_uint(lo)), "r"(__float_as_uint(hi)));
    return r;
}
static __device__ __forceinline__ void unpk2(uint64_t v, float& lo, float& hi) {
    uint32_t a, c;
    asm("mov.b64 {%0, %1}, %2;" : "=r"(a), "=r"(c) : "l"(v));
    lo = __uint_as_float(a); hi = __uint_as_float(c);
}
static __device__ __forceinline__ uint64_t add2(uint64_t a, uint64_t b) {
    uint64_t o; asm("add.rn.f32x2 %0, %1, %2;" : "=l"(o) : "l"(a), "l"(b)); return o;
}
static __device__ __forceinline__ uint64_t mul2(uint64_t a, uint64_t b) {
    uint64_t o; asm("mul.rn.f32x2 %0, %1, %2;" : "=l"(o) : "l"(a), "l"(b)); return o;
}
static __device__ __forceinline__ uint64_t fma2(uint64_t a, uint64_t b, uint64_t c) {
    uint64_t o; asm("fma.rn.f32x2 %0, %1, %2, %3;" : "=l"(o) : "l"(a), "l"(b), "l"(c)); return o;
}

// ---------------- FPS: one 2-CTA cluster per batch ----------------
__global__ __launch_bounds__(T, 1) __cluster_dims__(CL, 1, 1)
void fps_kernel(const float* __restrict__ xyz, const int* __restrict__ label)
{
    extern __shared__ char smem[];
    float* s_x   = (float*)(smem + OFF_X);
    float* s_y   = (float*)(smem + OFF_Y);
    float* s_z   = (float*)(smem + OFF_Z);
    float* s_cnt = (float*)(smem + OFF_CNT);
    unsigned long long* s_warp = (unsigned long long*)(smem + OFF_WARP);
    uint32_t* s_cand = (uint32_t*)(smem + OFF_CAND);   // [buf][6]: sc,gi,x,y,z,seq
    float4* s_win = (float4*)(smem + OFF_WIN);

    const int b    = blockIdx.x / CL;
    const int rank = blockIdx.x % CL;
    const int peer = rank ^ 1;
    const int tid  = threadIdx.x;
    const int base = rank * NLOC;
    const float* bx = xyz + (size_t)b * NN * 3;
    const int*   bl = label + (size_t)b * NN;

    const uint32_t cand_a = smem_u32(s_cand);
    const uint32_t dstbuf0 = mapa_u32(cand_a,      (uint32_t)peer);
    const uint32_t dstbuf1 = mapa_u32(cand_a + 24, (uint32_t)peer);

    if (tid < 32) s_cnt[tid] = 0.0f;
    if (tid < 12) s_cand[tid] = 0u;      // seq words start at 0; s >= 1
    __syncthreads();

    // Class histogram over the FULL batch + stage this CTA's coord shard.
    for (int i = tid; i < NN; i += T) atomicAdd(&s_cnt[bl[i]], 1.0f);
    for (int i = tid; i < NLOC; i += T) {
        int g = base + i;
        s_x[i] = bx[3 * g + 0];
        s_y[i] = bx[3 * g + 1];
        s_z[i] = bx[3 * g + 2];
    }
    __syncthreads();

    // Register-resident packed coords/weights. Pair j holds points
    // p0 = tid + (2j)*T, p1 = tid + (2j+1)*T.
    uint64_t px[NPAIR], py[NPAIR], pz[NPAIR], pw[NPAIR];
    float M[PPT];
    #pragma unroll
    for (int j = 0; j < NPAIR; j++) {
        int p0 = tid + (2 * j) * T, p1 = tid + (2 * j + 1) * T;
        px[j] = pk2(s_x[p0], s_x[p1]);
        py[j] = pk2(s_y[p0], s_y[p1]);
        pz[j] = pk2(s_z[p0], s_z[p1]);
        float w0 = s_cnt[bl[base + p0]], w1 = s_cnt[bl[base + p1]];
        pw[j] = pk2(w0, w1);
        M[2 * j]     = 1e10f * w0;      // matches min(1e10,d)*w after iter 1
        M[2 * j + 1] = 1e10f * w1;
    }

    float cx = bx[0], cy = bx[1], cz = bx[2];
    if (rank == 0 && tid == 0) g_idx[b * SS] = 0;

    const int wid = tid >> 5, lane = tid & 31;

    // Peers' smem must be zeroed before any cross-CTA store.
    asm volatile("barrier.cluster.arrive.aligned;" ::: "memory");
    asm volatile("barrier.cluster.wait.aligned;" ::: "memory");

    for (int s = 1; s < SS; s++) {
        const uint64_t ncx = pk2(-cx, -cx);
        const uint64_t ncy = pk2(-cy, -cy);
        const uint64_t ncz = pk2(-cz, -cz);

        // ---- Phase 1: packed distance + min update; track max score ----
        float best = 0.0f;                       // scores >= 0
        #pragma unroll
        for (int j = 0; j < NPAIR; j++) {
            uint64_t dx = add2(px[j], ncx);      // rn(x - cx) per lane
            uint64_t dy = add2(py[j], ncy);
            uint64_t dz = add2(pz[j], ncz);
            uint64_t t  = mul2(dx, dx);          // XLA-contracted:
            t = fma2(dy, dy, t);                 // fma(dy,dy, dx*dx)
            t = fma2(dz, dz, t);                 // fma(dz,dz, ...)
            uint64_t dw = mul2(t, pw[j]);        // d * w
            float lo, hi; unpk2(dw, lo, hi);
            float m0 = fminf(M[2 * j],     lo);
            float m1 = fminf(M[2 * j + 1], hi);
            M[2 * j] = m0; M[2 * j + 1] = m1;
            best = fmaxf(best, m0);
            best = fmaxf(best, m1);
        }
        // ---- Phase 2: lowest local index attaining this thread's best ----
        int bi = 0x7fffffff;
        #pragma unroll
        for (int k = PPT - 1; k >= 0; k--)
            if (M[k] == best) bi = tid + k * T;

        // ---- Warp reduce (u32 max on non-negative score bits; min idx) ----
        uint32_t sb  = __float_as_uint(best);
        uint32_t smx = redux_max_u32(sb);
        unsigned bio = __reduce_min_sync(0xffffffffu,
                         (sb == smx) ? (unsigned)bi : 0x7fffffffu);
        if (lane == 0)
            s_warp[wid] = (((unsigned long long)smx) << 32) | (unsigned long long)bio;
        __syncthreads();

        // ---- Warp 0: CTA reduce + pairwise cluster exchange ----
        if (wid == 0) {
            unsigned long long pk = (lane < NW) ? s_warp[lane] : 0ULL;
            uint32_t sc = (uint32_t)(pk >> 32);
            uint32_t li = (lane < NW) ? (uint32_t)pk : 0x7fffffffu;
            uint32_t cmax = redux_max_u32(sc);
            uint32_t lmin = __reduce_min_sync(0xffffffffu,
                              (sc == cmax) ? li : 0x7fffffffu);
            // CTA winner: score cmax, local idx lmin, global idx gi.
            int      gi = base + (int)lmin;
            float    wxx = s_x[lmin], wyy = s_y[lmin], wzz = s_z[lmin];

            if (lane == 0) {
                // Send record to peer: [sc, gi] [x, y] [z, seq(release)]
                uint32_t dst = (s & 1) ? dstbuf1 : dstbuf0;
                st_cl_u64(dst + 0,  ((uint64_t)(uint32_t)gi << 32) | (uint64_t)cmax);
                st_cl_u64(dst + 8,  ((uint64_t)__float_as_uint(wyy) << 32)
                                   | (uint64_t)__float_as_uint(wxx));
                st_cl_rel_u64(dst + 16, ((uint64_t)(uint32_t)s << 32)
                                   | (uint64_t)__float_as_uint(wzz));
            }
            // Poll own buffer for peer's record (whole warp, broadcast LDS).
            uint32_t bufo = (s & 1) ? 24u : 0u;
            while (ld_acq_u32(cand_a + bufo + 20) != (uint32_t)s) { }
            uint32_t psc = s_cand[(bufo >> 2) + 0];
            int      pgi = (int)s_cand[(bufo >> 2) + 1];
            float    pxx = __uint_as_float(s_cand[(bufo >> 2) + 2]);
            float    pyy = __uint_as_float(s_cand[(bufo >> 2) + 3]);
            float    pzz = __uint_as_float(s_cand[(bufo >> 2) + 4]);

            bool peer_wins = (psc > cmax) || (psc == cmax && pgi < gi);
            int    wg = peer_wins ? pgi : gi;
            float  wx = peer_wins ? pxx : wxx;
            float  wy = peer_wins ? pyy : wyy;
            float  wz = peer_wins ? pzz : wzz;
            if (lane == 0) {
                *s_win = make_float4(wx, wy, wz, __uint_as_float((uint32_t)wg));
                if (rank == 0) g_idx[b * SS + s] = wg;
            }
        }
        __syncthreads();
        float4 wr = *s_win;
        cx = wr.x; cy = wr.y; cz = wr.z;
    }

    // Keep cluster alive until all remote traffic has retired.
    asm volatile("barrier.cluster.arrive.aligned;" ::: "memory");
    asm volatile("barrier.cluster.wait.aligned;" ::: "memory");
}

// ---------------- Gather ----------------
__global__ void gather_kernel(const float* __restrict__ xyz,
                              const float* __restrict__ feat,
                              const int*   __restrict__ label,
                              float* __restrict__ out)
{
    int i = blockIdx.x * blockDim.x + threadIdx.x;
    const int total = A0 + A1 + A2;
    if (i >= total) return;

    if (i < A0) {
        int b = i / (SS * 3);
        int r = i - b * SS * 3;
        int s = r / 3;
        int d = r - s * 3;
        int id = g_idx[b * SS + s];
        out[i] = xyz[((size_t)b * NN + id) * 3 + d];
    } else if (i < A0 + A1) {
        int j = i - A0;
        int b = j / (CC * SS);
        int r = j - b * CC * SS;
        int c = r / SS;
        int s = r - c * SS;
        int id = g_idx[b * SS + s];
        out[i] = feat[((size_t)b * CC + c) * NN + id];
    } else {
        int j = i - A0 - A1;
        int b = j / SS;
        int s = j - b * SS;
        int id = g_idx[b * SS + s];
        out[i] = (float)label[(size_t)b * NN + id];
    }
}

extern "C" void kernel_launch(void* const* d_in, const int* in_sizes, int n_in,
                              void* d_out, int out_size)
{
    const float* xyz   = (const float*)d_in[0];
    const float* feat  = (const float*)d_in[1];
    const int*   label = (const int*)  d_in[2];
    float*       out   = (float*)d_out;

    cudaFuncSetAttribute(fps_kernel,
                         cudaFuncAttributeMaxDynamicSharedMemorySize,
                         SMEM_BYTES);

    fps_kernel<<<BB * CL, T, SMEM_BYTES>>>(xyz, label);

    const int total = A0 + A1 + A2;
    gather_kernel<<<(total + 255) / 256, 256>>>(xyz, feat, label, out);
}

// round 10
// speedup vs baseline: 1.4265x; 1.0828x over previous
#include <cuda_runtime.h>
#include <cstdint>

// Problem constants
#define BB  16
#define NN  16384
#define SS  1024
#define CC  128
#define SEM 20

// Cluster FPS config
#define CL   2               // CTAs per cluster (one cluster per batch)
#define T    512             // threads per CTA
#define NLOC (NN / CL)       // 8192 points per CTA
#define PPT  (NLOC / T)      // 16 points per thread
#define NPAIR (PPT / 2)      // 8 packed pairs per thread
#define NW   (T / 32)        // 16 warps

#define A0 (BB * SS * 3)
#define A1 (BB * CC * SS)
#define A2 (BB * SS)

__device__ int g_idx[BB * SS];

// Dynamic smem layout (bytes)
#define OFF_X    0
#define OFF_Y    (NLOC * 4)
#define OFF_Z    (NLOC * 8)
#define OFF_CNT  (NLOC * 12)            // 32 floats
#define OFF_WARP (OFF_CNT + 128)        // 2 bufs x 16 x u64 {score, idx}
#define OFF_CAND (OFF_WARP + 256)       // 2 bufs x 24B peer records
#define SMEM_BYTES (OFF_CAND + 64)

// ---------------- PTX helpers ----------------
static __device__ __forceinline__ uint32_t smem_u32(const void* p) {
    uint32_t a;
    asm("{ .reg .u64 t; cvta.to.shared.u64 t, %1; cvt.u32.u64 %0, t; }"
        : "=r"(a) : "l"(p));
    return a;
}
static __device__ __forceinline__ uint32_t mapa_u32(uint32_t a, uint32_t rank) {
    uint32_t d;
    asm("mapa.shared::cluster.u32 %0, %1, %2;" : "=r"(d) : "r"(a), "r"(rank));
    return d;
}
static __device__ __forceinline__ void st_cl_u64(uint32_t a, uint64_t v) {
    asm volatile("st.shared::cluster.b64 [%0], %1;" :: "r"(a), "l"(v) : "memory");
}
static __device__ __forceinline__ void st_cl_rel_u64(uint32_t a, uint64_t v) {
    asm volatile("st.release.cluster.shared::cluster.b64 [%0], %1;"
                 :: "r"(a), "l"(v) : "memory");
}
static __device__ __forceinline__ uint32_t ld_acq_u32(uint32_t a) {
    uint32_t v;
    asm volatile("ld.acquire.cluster.shared::cta.b32 %0, [%1];"
                 : "=r"(v) : "r"(a) : "memory");
    return v;
}
static __device__ __forceinline__ uint32_t redux_max_u32(uint32_t v) {
    uint32_t o;
    asm volatile("redux.sync.max.u32 %0, %1, 0xffffffff;" : "=r"(o) : "r"(v));
    return o;
}
// Packed f32x2 (per-lane bitwise identical to scalar rn ops)
static __device__ __forceinline__ uint64_t pk2(float lo, float hi) {
    uint64_t r;
    asm("mov.b64 %0, {%1, %2};"
        : "=l"(r) : "r"(__float_as_uint(lo)), "r"(__float_as_uint(hi)));
    return r;
}
static __device__ __forceinline__ void unpk2(uint64_t v, float& lo, float& hi) {
    uint32_t a, c;
    asm("mov.b64 {%0, %1}, %2;" : "=r"(a), "=r"(c) : "l"(v));
    lo = __uint_as_float(a); hi = __uint_as_float(c);
}
static __device__ __forceinline__ uint64_t add2(uint64_t a, uint64_t b) {
    uint64_t o; asm("add.rn.f32x2 %0, %1, %2;" : "=l"(o) : "l"(a), "l"(b)); return o;
}
static __device__ __forceinline__ uint64_t mul2(uint64_t a, uint64_t b) {
    uint64_t o; asm("mul.rn.f32x2 %0, %1, %2;" : "=l"(o) : "l"(a), "l"(b)); return o;
}
static __device__ __forceinline__ uint64_t fma2(uint64_t a, uint64_t b, uint64_t c) {
    uint64_t o; asm("fma.rn.f32x2 %0, %1, %2, %3;" : "=l"(o) : "l"(a), "l"(b), "l"(c)); return o;
}

// ---------------- FPS: one 2-CTA cluster per batch ----------------
__global__ __launch_bounds__(T, 1) __cluster_dims__(CL, 1, 1)
void fps_kernel(const float* __restrict__ xyz, const int* __restrict__ label)
{
    extern __shared__ char smem[];
    float* s_x   = (float*)(smem + OFF_X);
    float* s_y   = (float*)(smem + OFF_Y);
    float* s_z   = (float*)(smem + OFF_Z);
    float* s_cnt = (float*)(smem + OFF_CNT);
    unsigned long long* s_warp = (unsigned long long*)(smem + OFF_WARP);
    uint32_t* s_cand = (uint32_t*)(smem + OFF_CAND);   // [buf][6]: sc,gi,x,y,z,seq

    const int b    = blockIdx.x / CL;
    const int rank = blockIdx.x % CL;
    const int peer = rank ^ 1;
    const int tid  = threadIdx.x;
    const int base = rank * NLOC;
    const float* bx = xyz + (size_t)b * NN * 3;
    const int*   bl = label + (size_t)b * NN;

    const uint32_t cand_a  = smem_u32(s_cand);
    const uint32_t dstbuf0 = mapa_u32(cand_a,      (uint32_t)peer);
    const uint32_t dstbuf1 = mapa_u32(cand_a + 24, (uint32_t)peer);

    if (tid < 32) s_cnt[tid] = 0.0f;
    if (tid < 12) s_cand[tid] = 0u;      // seq words start at 0; s >= 1
    __syncthreads();

    // Class histogram over the FULL batch + stage this CTA's coord shard.
    for (int i = tid; i < NN; i += T) atomicAdd(&s_cnt[bl[i]], 1.0f);
    for (int i = tid; i < NLOC; i += T) {
        int g = base + i;
        s_x[i] = bx[3 * g + 0];
        s_y[i] = bx[3 * g + 1];
        s_z[i] = bx[3 * g + 2];
    }
    __syncthreads();

    // Register-resident packed coords/weights. Pair j holds points
    // p0 = tid + (2j)*T, p1 = tid + (2j+1)*T.
    uint64_t px[NPAIR], py[NPAIR], pz[NPAIR], pw[NPAIR];
    float M[PPT];
    #pragma unroll
    for (int j = 0; j < NPAIR; j++) {
        int p0 = tid + (2 * j) * T, p1 = tid + (2 * j + 1) * T;
        px[j] = pk2(s_x[p0], s_x[p1]);
        py[j] = pk2(s_y[p0], s_y[p1]);
        pz[j] = pk2(s_z[p0], s_z[p1]);
        float w0 = s_cnt[bl[base + p0]], w1 = s_cnt[bl[base + p1]];
        pw[j] = pk2(w0, w1);
        M[2 * j]     = 1e10f * w0;      // matches min(1e10,d)*w after iter 1
        M[2 * j + 1] = 1e10f * w1;
    }

    float cx = bx[0], cy = bx[1], cz = bx[2];
    if (rank == 0 && tid == 0) g_idx[b * SS] = 0;

    const int wid = tid >> 5, lane = tid & 31;

    // Peers' smem must be initialized before any cross-CTA store.
    asm volatile("barrier.cluster.arrive.aligned;" ::: "memory");
    asm volatile("barrier.cluster.wait.aligned;" ::: "memory");

    for (int s = 1; s < SS; s++) {
        const uint64_t ncx = pk2(-cx, -cx);
        const uint64_t ncy = pk2(-cy, -cy);
        const uint64_t ncz = pk2(-cz, -cz);

        // ---- Phase 1: packed distance + min update; track max score ----
        float best = 0.0f;                       // scores >= 0
        #pragma unroll
        for (int j = 0; j < NPAIR; j++) {
            uint64_t dx = add2(px[j], ncx);      // rn(x - cx) per lane
            uint64_t dy = add2(py[j], ncy);
            uint64_t dz = add2(pz[j], ncz);
            uint64_t t  = mul2(dx, dx);          // XLA-contracted:
            t = fma2(dy, dy, t);                 // fma(dy,dy, dx*dx)
            t = fma2(dz, dz, t);                 // fma(dz,dz, ...)
            uint64_t dw = mul2(t, pw[j]);        // d * w
            float lo, hi; unpk2(dw, lo, hi);
            float m0 = fminf(M[2 * j],     lo);
            float m1 = fminf(M[2 * j + 1], hi);
            M[2 * j] = m0; M[2 * j + 1] = m1;
            best = fmaxf(best, m0);
            best = fmaxf(best, m1);
        }
        // ---- Phase 2: lowest local index attaining this thread's best ----
        int bi = 0x7fffffff;
        #pragma unroll
        for (int k = PPT - 1; k >= 0; k--)
            if (M[k] == best) bi = tid + k * T;

        // ---- Warp reduce (u32 max on non-negative score bits; min idx) ----
        uint32_t sb  = __float_as_uint(best);
        uint32_t smx = redux_max_u32(sb);
        unsigned bio = __reduce_min_sync(0xffffffffu,
                         (sb == smx) ? (unsigned)bi : 0x7fffffffu);
        // Double-buffered by parity: fast warps may STS iter s+1 while slow
        // warps still read iter s.
        unsigned long long* swb = &s_warp[(s & 1) * NW];
        if (lane == 0)
            swb[wid] = (((unsigned long long)smx) << 32) | (unsigned long long)bio;
        __syncthreads();   // the ONLY barrier in the iteration

        // ---- EVERY warp redundantly: CTA reduce, (warp0: send), poll, compare
        unsigned long long pk = (lane < NW) ? swb[lane] : 0ULL;
        uint32_t sc = (uint32_t)(pk >> 32);
        uint32_t li = (lane < NW) ? (uint32_t)pk : 0x7fffffffu;
        uint32_t cmax = redux_max_u32(sc);
        uint32_t lmin = __reduce_min_sync(0xffffffffu,
                          (sc == cmax) ? li : 0x7fffffffu);
        int   gi  = base + (int)lmin;
        float wxx = s_x[lmin], wyy = s_y[lmin], wzz = s_z[lmin];

        if (wid == 0 && lane == 0) {
            // Send record to peer: [sc, gi] [x, y] [z, seq(release)]
            uint32_t dst = (s & 1) ? dstbuf1 : dstbuf0;
            st_cl_u64(dst + 0,  ((uint64_t)(uint32_t)gi << 32) | (uint64_t)cmax);
            st_cl_u64(dst + 8,  ((uint64_t)__float_as_uint(wyy) << 32)
                               | (uint64_t)__float_as_uint(wxx));
            st_cl_rel_u64(dst + 16, ((uint64_t)(uint32_t)s << 32)
                               | (uint64_t)__float_as_uint(wzz));
        }

        // Each warp polls its own smem for the peer record of this iter.
        uint32_t bufo = (s & 1) ? 24u : 0u;
        while (ld_acq_u32(cand_a + bufo + 20) != (uint32_t)s) { }
        uint32_t psc = s_cand[(bufo >> 2) + 0];
        int      pgi = (int)s_cand[(bufo >> 2) + 1];
        float    pxx = __uint_as_float(s_cand[(bufo >> 2) + 2]);
        float    pyy = __uint_as_float(s_cand[(bufo >> 2) + 3]);
        float    pzz = __uint_as_float(s_cand[(bufo >> 2) + 4]);

        bool peer_wins = (psc > cmax) || (psc == cmax && pgi < gi);
        int wg = peer_wins ? pgi : gi;
        cx = peer_wins ? pxx : wxx;
        cy = peer_wins ? pyy : wyy;
        cz = peer_wins ? pzz : wzz;
        if (rank == 0 && wid == 0 && lane == 0) g_idx[b * SS + s] = wg;
    }

    // Keep cluster alive until all remote traffic has retired.
    asm volatile("barrier.cluster.arrive.aligned;" ::: "memory");
    asm volatile("barrier.cluster.wait.aligned;" ::: "memory");
}

// ---------------- Gather ----------------
__global__ void gather_kernel(const float* __restrict__ xyz,
                              const float* __restrict__ feat,
                              const int*   __restrict__ label,
                              float* __restrict__ out)
{
    int i = blockIdx.x * blockDim.x + threadIdx.x;
    const int total = A0 + A1 + A2;
    if (i >= total) return;

    if (i < A0) {
        int b = i / (SS * 3);
        int r = i - b * SS * 3;
        int s = r / 3;
        int d = r - s * 3;
        int id = g_idx[b * SS + s];
        out[i] = xyz[((size_t)b * NN + id) * 3 + d];
    } else if (i < A0 + A1) {
        int j = i - A0;
        int b = j / (CC * SS);
        int r = j - b * CC * SS;
        int c = r / SS;
        int s = r - c * SS;
        int id = g_idx[b * SS + s];
        out[i] = feat[((size_t)b * CC + c) * NN + id];
    } else {
        int j = i - A0 - A1;
        int b = j / SS;
        int s = j - b * SS;
        int id = g_idx[b * SS + s];
        out[i] = (float)label[(size_t)b * NN + id];
    }
}

extern "C" void kernel_launch(void* const* d_in, const int* in_sizes, int n_in,
                              void* d_out, int out_size)
{
    const float* xyz   = (const float*)d_in[0];
    const float* feat  = (const float*)d_in[1];
    const int*   label = (const int*)  d_in[2];
    float*       out   = (float*)d_out;

    cudaFuncSetAttribute(fps_kernel,
                         cudaFuncAttributeMaxDynamicSharedMemorySize,
                         SMEM_BYTES);

    fps_kernel<<<BB * CL, T, SMEM_BYTES>>>(xyz, label);

    const int total = A0 + A1 + A2;
    gather_kernel<<<(total + 255) / 256, 256>>>(xyz, feat, label, out);
}

// round 13
// speedup vs baseline: 1.5568x; 1.0914x over previous
#include <cuda_runtime.h>
#include <cstdint>

// Problem constants
#define BB  16
#define NN  16384
#define SS  1024
#define CC  128
#define SEM 20

// Cluster FPS config
#define CL   4               // CTAs per cluster (one cluster per batch)
#define T    512             // threads per CTA
#define NLOC (NN / CL)       // 4096 points per CTA
#define PPT  (NLOC / T)      // 8 points per thread
#define NPAIR (PPT / 2)      // 4 packed pairs per thread
#define NW   (T / 32)        // 16 warps

#define A0 (BB * SS * 3)
#define A1 (BB * CC * SS)
#define A2 (BB * SS)

__device__ int g_idx[BB * SS];

// Dynamic smem layout (bytes)
#define OFF_X    0
#define OFF_Y    (NLOC * 4)
#define OFF_Z    (NLOC * 8)
#define OFF_CNT  (NLOC * 12)            // 32 floats
#define OFF_WARP (OFF_CNT + 128)        // 2 bufs x 16 x u64 {score, idx}
#define OFF_CAND (OFF_WARP + 256)       // [2 parity][4 slots][24B records]
#define SMEM_BYTES (OFF_CAND + 192)

// ---------------- PTX helpers ----------------
static __device__ __forceinline__ uint32_t smem_u32(const void* p) {
    uint32_t a;
    asm("{ .reg .u64 t; cvta.to.shared.u64 t, %1; cvt.u32.u64 %0, t; }"
        : "=r"(a) : "l"(p));
    return a;
}
static __device__ __forceinline__ uint32_t mapa_u32(uint32_t a, uint32_t rank) {
    uint32_t d;
    asm("mapa.shared::cluster.u32 %0, %1, %2;" : "=r"(d) : "r"(a), "r"(rank));
    return d;
}
static __device__ __forceinline__ void st_cl_u64(uint32_t a, uint64_t v) {
    asm volatile("st.shared::cluster.b64 [%0], %1;" :: "r"(a), "l"(v) : "memory");
}
static __device__ __forceinline__ void st_cl_rel_u64(uint32_t a, uint64_t v) {
    asm volatile("st.release.cluster.shared::cluster.b64 [%0], %1;"
                 :: "r"(a), "l"(v) : "memory");
}
static __device__ __forceinline__ uint32_t ld_acq_u32(uint32_t a) {
    uint32_t v;
    asm volatile("ld.acquire.cluster.shared::cta.b32 %0, [%1];"
                 : "=r"(v) : "r"(a) : "memory");
    return v;
}
static __device__ __forceinline__ uint32_t redux_max_u32(uint32_t v) {
    uint32_t o;
    asm volatile("redux.sync.max.u32 %0, %1, 0xffffffff;" : "=r"(o) : "r"(v));
    return o;
}
// Packed f32x2 (per-lane bitwise identical to scalar rn ops)
static __device__ __forceinline__ uint64_t pk2(float lo, float hi) {
    uint64_t r;
    asm("mov.b64 %0, {%1, %2};"
        : "=l"(r) : "r"(__float_as_uint(lo)), "r"(__float_as_uint(hi)));
    return r;
}
static __device__ __forceinline__ void unpk2(uint64_t v, float& lo, float& hi) {
    uint32_t a, c;
    asm("mov.b64 {%0, %1}, %2;" : "=r"(a), "=r"(c) : "l"(v));
    lo = __uint_as_float(a); hi = __uint_as_float(c);
}
static __device__ __forceinline__ uint64_t add2(uint64_t a, uint64_t b) {
    uint64_t o; asm("add.rn.f32x2 %0, %1, %2;" : "=l"(o) : "l"(a), "l"(b)); return o;
}
static __device__ __forceinline__ uint64_t mul2(uint64_t a, uint64_t b) {
    uint64_t o; asm("mul.rn.f32x2 %0, %1, %2;" : "=l"(o) : "l"(a), "l"(b)); return o;
}
static __device__ __forceinline__ uint64_t fma2(uint64_t a, uint64_t b, uint64_t c) {
    uint64_t o; asm("fma.rn.f32x2 %0, %1, %2, %3;" : "=l"(o) : "l"(a), "l"(b), "l"(c)); return o;
}

// ---------------- FPS: one 4-CTA cluster per batch ----------------
__global__ __launch_bounds__(T, 1) __cluster_dims__(CL, 1, 1)
void fps_kernel(const float* __restrict__ xyz, const int* __restrict__ label)
{
    extern __shared__ char smem[];
    float* s_x   = (float*)(smem + OFF_X);
    float* s_y   = (float*)(smem + OFF_Y);
    float* s_z   = (float*)(smem + OFF_Z);
    float* s_cnt = (float*)(smem + OFF_CNT);
    unsigned long long* s_warp = (unsigned long long*)(smem + OFF_WARP);
    uint32_t* s_cand = (uint32_t*)(smem + OFF_CAND);  // [par][slot][6]: sc,gi,x,y,z,seq

    const int b    = blockIdx.x / CL;
    const int rank = blockIdx.x % CL;
    const int tid  = threadIdx.x;
    const int base = rank * NLOC;
    const float* bx = xyz + (size_t)b * NN * 3;
    const int*   bl = label + (size_t)b * NN;

    const uint32_t cand_a = smem_u32(s_cand);

    if (tid < 32) s_cnt[tid] = 0.0f;
    if (tid < 48) s_cand[tid] = 0u;      // all seq words 0; s >= 1
    __syncthreads();

    // Class histogram over the FULL batch + stage this CTA's coord shard.
    for (int i = tid; i < NN; i += T) atomicAdd(&s_cnt[bl[i]], 1.0f);
    for (int i = tid; i < NLOC; i += T) {
        int g = base + i;
        s_x[i] = bx[3 * g + 0];
        s_y[i] = bx[3 * g + 1];
        s_z[i] = bx[3 * g + 2];
    }
    __syncthreads();

    // Register-resident packed coords/weights. Pair j holds points
    // p0 = tid + (2j)*T, p1 = tid + (2j+1)*T.
    uint64_t px[NPAIR], py[NPAIR], pz[NPAIR], pw[NPAIR];
    float M[PPT];
    #pragma unroll
    for (int j = 0; j < NPAIR; j++) {
        int p0 = tid + (2 * j) * T, p1 = tid + (2 * j + 1) * T;
        px[j] = pk2(s_x[p0], s_x[p1]);
        py[j] = pk2(s_y[p0], s_y[p1]);
        pz[j] = pk2(s_z[p0], s_z[p1]);
        float w0 = s_cnt[bl[base + p0]], w1 = s_cnt[bl[base + p1]];
        pw[j] = pk2(w0, w1);
        M[2 * j]     = 1e10f * w0;      // matches min(1e10,d)*w after iter 1
        M[2 * j + 1] = 1e10f * w1;
    }

    float cx = bx[0], cy = bx[1], cz = bx[2];
    if (rank == 0 && tid == 0) g_idx[b * SS] = 0;

    const int wid = tid >> 5, lane = tid & 31;

    // Remote record destinations: warp-0 lanes 0..2 each serve one peer.
    // Record written into the RECEIVER's buffer at slot index == MY rank.
    uint32_t dst0 = 0, dst1 = 0;
    if (wid == 0 && lane < CL - 1) {
        uint32_t peer = (uint32_t)((rank + 1 + lane) % CL);
        dst0 = mapa_u32(cand_a + (uint32_t)(rank * 24),            peer);
        dst1 = mapa_u32(cand_a + (uint32_t)((CL + rank) * 24),     peer);
    }

    // Peers' smem must be initialized before any cross-CTA store.
    asm volatile("barrier.cluster.arrive.aligned;" ::: "memory");
    asm volatile("barrier.cluster.wait.aligned;" ::: "memory");

    for (int s = 1; s < SS; s++) {
        const uint64_t ncx = pk2(-cx, -cx);
        const uint64_t ncy = pk2(-cy, -cy);
        const uint64_t ncz = pk2(-cz, -cz);

        // ---- Phase 1: packed distance + min update; track max score ----
        float best = 0.0f;                       // scores >= 0
        #pragma unroll
        for (int j = 0; j < NPAIR; j++) {
            uint64_t dx = add2(px[j], ncx);      // rn(x - cx) per lane
            uint64_t dy = add2(py[j], ncy);
            uint64_t dz = add2(pz[j], ncz);
            uint64_t t  = mul2(dx, dx);          // XLA-contracted:
            t = fma2(dy, dy, t);                 // fma(dy,dy, dx*dx)
            t = fma2(dz, dz, t);                 // fma(dz,dz, ...)
            uint64_t dw = mul2(t, pw[j]);        // d * w
            float lo, hi; unpk2(dw, lo, hi);
            float m0 = fminf(M[2 * j],     lo);
            float m1 = fminf(M[2 * j + 1], hi);
            M[2 * j] = m0; M[2 * j + 1] = m1;
            best = fmaxf(best, m0);
            best = fmaxf(best, m1);
        }
        // ---- Phase 2: lowest local index attaining this thread's best ----
        int bi = 0x7fffffff;
        #pragma unroll
        for (int k = PPT - 1; k >= 0; k--)
            if (M[k] == best) bi = tid + k * T;

        // ---- Warp reduce (u32 max on non-negative score bits; min idx) ----
        uint32_t sb  = __float_as_uint(best);
        uint32_t smx = redux_max_u32(sb);
        unsigned bio = __reduce_min_sync(0xffffffffu,
                         (sb == smx) ? (unsigned)bi : 0x7fffffffu);
        unsigned long long* swb = &s_warp[(s & 1) * NW];   // parity buffered
        if (lane == 0)
            swb[wid] = (((unsigned long long)smx) << 32) | (unsigned long long)bio;
        __syncthreads();   // the ONLY barrier in the iteration

        // ---- EVERY warp redundantly: CTA reduce; warp0 lanes 0-2 send ----
        unsigned long long pkd = (lane < NW) ? swb[lane] : 0ULL;
        uint32_t sc = (uint32_t)(pkd >> 32);
        uint32_t li = (lane < NW) ? (uint32_t)pkd : 0x7fffffffu;
        uint32_t cmax = redux_max_u32(sc);
        uint32_t lmin = __reduce_min_sync(0xffffffffu,
                          (sc == cmax) ? li : 0x7fffffffu);
        int   gi  = base + (int)lmin;
        float wxx = s_x[lmin], wyy = s_y[lmin], wzz = s_z[lmin];

        if (wid == 0 && lane < CL - 1) {
            // 3 lanes send in parallel: [sc, gi] [x, y] [z, seq(release)]
            uint32_t dst = (s & 1) ? dst1 : dst0;
            st_cl_u64(dst + 0,  ((uint64_t)(uint32_t)gi << 32) | (uint64_t)cmax);
            st_cl_u64(dst + 8,  ((uint64_t)__float_as_uint(wyy) << 32)
                               | (uint64_t)__float_as_uint(wxx));
            st_cl_rel_u64(dst + 16, ((uint64_t)(uint32_t)s << 32)
                               | (uint64_t)__float_as_uint(wzz));
        }

        // ---- Poll the 3 peer slots in own smem; reduce 4 candidates ----
        uint32_t bufw = (uint32_t)((s & 1) * CL * 6);      // word offset of parity buf
        uint32_t Wsc = cmax; int Wgi = gi;
        float Wx = wxx, Wy = wyy, Wz = wzz;
        #pragma unroll
        for (int j = 0; j < CL - 1; j++) {
            uint32_t slot = (uint32_t)((rank + 1 + j) % CL);
            uint32_t wo   = bufw + slot * 6;
            while (ld_acq_u32(cand_a + (wo + 5) * 4) != (uint32_t)s) { }
            uint32_t psc = s_cand[wo + 0];
            int      pgi = (int)s_cand[wo + 1];
            if (psc > Wsc || (psc == Wsc && pgi < Wgi)) {
                Wsc = psc; Wgi = pgi;
                Wx = __uint_as_float(s_cand[wo + 2]);
                Wy = __uint_as_float(s_cand[wo + 3]);
                Wz = __uint_as_float(s_cand[wo + 4]);
            }
        }
        cx = Wx; cy = Wy; cz = Wz;
        if (rank == 0 && wid == 0 && lane == 0) g_idx[b * SS + s] = Wgi;
    }

    // Keep cluster alive until all remote traffic has retired.
    asm volatile("barrier.cluster.arrive.aligned;" ::: "memory");
    asm volatile("barrier.cluster.wait.aligned;" ::: "memory");
}

// ---------------- Gather ----------------
__global__ void gather_kernel(const float* __restrict__ xyz,
                              const float* __restrict__ feat,
                              const int*   __restrict__ label,
                              float* __restrict__ out)
{
    int i = blockIdx.x * blockDim.x + threadIdx.x;
    const int total = A0 + A1 + A2;
    if (i >= total) return;

    if (i < A0) {
        int b = i / (SS * 3);
        int r = i - b * SS * 3;
        int s = r / 3;
        int d = r - s * 3;
        int id = g_idx[b * SS + s];
        out[i] = xyz[((size_t)b * NN + id) * 3 + d];
    } else if (i < A0 + A1) {
        int j = i - A0;
        int b = j / (CC * SS);
        int r = j - b * CC * SS;
        int c = r / SS;
        int s = r - c * SS;
        int id = g_idx[b * SS + s];
        out[i] = feat[((size_t)b * CC + c) * NN + id];
    } else {
        int j = i - A0 - A1;
        int b = j / SS;
        int s = j - b * SS;
        int id = g_idx[b * SS + s];
        out[i] = (float)label[(size_t)b * NN + id];
    }
}

extern "C" void kernel_launch(void* const* d_in, const int* in_sizes, int n_in,
                              void* d_out, int out_size)
{
    const float* xyz   = (const float*)d_in[0];
    const float* feat  = (const float*)d_in[1];
    const int*   label = (const int*)  d_in[2];
    float*       out   = (float*)d_out;

    cudaFuncSetAttribute(fps_kernel,
                         cudaFuncAttributeMaxDynamicSharedMemorySize,
                         SMEM_BYTES);

    fps_kernel<<<BB * CL, T, SMEM_BYTES>>>(xyz, label);

    const int total = A0 + A1 + A2;
    gather_kernel<<<(total + 255) / 256, 256>>>(xyz, feat, label, out);
}